// round 1
// baseline (speedup 1.0000x reference)
#include <cuda_runtime.h>
#include <cuda_bf16.h>
#include <cstdint>

#define BB    2
#define LQ    4096
#define CDIM  768
#define GH    64
#define GW    64
#define NHEAD 6
#define NPNT  4
#define HD    128
#define MROWS 8192      // B*Lq == B*H*W
#define NOA   72        // packed off(48) + attn(24) columns

// ---------------- scratch (device globals; no allocation allowed) -------------
__device__ __align__(16) __nv_bfloat16 g_q[MROWS * CDIM];
__device__ __align__(16) __nv_bfloat16 g_f[MROWS * CDIM];
__device__ __align__(16) __nv_bfloat16 g_value[MROWS * CDIM];
__device__ __align__(16) __nv_bfloat16 g_sampled[MROWS * CDIM];
__device__ __align__(16) float         g_raw[MROWS * NOA];
__device__ __align__(16) __nv_bfloat16 g_wv[CDIM * CDIM];
__device__ __align__(16) __nv_bfloat16 g_wo[CDIM * CDIM];
__device__ __align__(16) __nv_bfloat16 g_woa[CDIM * NOA];
__device__ __align__(16) float         g_boa[NOA];

// ---------------- weight conversion / packing --------------------------------
__global__ void prep_kernel(const float* __restrict__ wv, const float* __restrict__ wo,
                            const float* __restrict__ woff, const float* __restrict__ watt,
                            const float* __restrict__ boff, const float* __restrict__ batt) {
    int i = blockIdx.x * 256 + threadIdx.x;
    if (i < CDIM * CDIM) {
        g_wv[i] = __float2bfloat16(wv[i]);
        g_wo[i] = __float2bfloat16(wo[i]);
    }
    if (i < CDIM * NOA) {
        int k = i / NOA, c = i % NOA;
        float v = (c < 48) ? woff[k * 48 + c] : watt[k * 24 + (c - 48)];
        g_woa[i] = __float2bfloat16(v);
    }
    if (i < NOA) g_boa[i] = (i < 48) ? boff[i] : batt[i - 48];
}

// ---------------- fused dual LayerNorm (x -> q, feat -> f), fp32 -> bf16 ------
__global__ void ln_kernel(const float* __restrict__ x, const float* __restrict__ feat,
                          const float* __restrict__ qw, const float* __restrict__ qb,
                          const float* __restrict__ fw, const float* __restrict__ fb) {
    int row = blockIdx.x;          // 0..16383
    int t = threadIdx.x;           // 256 threads, 3 elems each
    const float *src, *w, *bb;
    __nv_bfloat16* dst;
    if (row < MROWS) {
        src = x + (long)row * CDIM; w = qw; bb = qb; dst = g_q + (long)row * CDIM;
    } else {
        int r = row - MROWS;
        src = feat + (long)r * CDIM; w = fw; bb = fb; dst = g_f + (long)r * CDIM;
    }
    float v0 = src[t], v1 = src[t + 256], v2 = src[t + 512];
    float s  = v0 + v1 + v2;
    float ss = v0 * v0 + v1 * v1 + v2 * v2;
    #pragma unroll
    for (int o = 16; o > 0; o >>= 1) {
        s  += __shfl_xor_sync(0xffffffffu, s,  o);
        ss += __shfl_xor_sync(0xffffffffu, ss, o);
    }
    __shared__ float sm[16];
    if ((t & 31) == 0) { sm[t >> 5] = s; sm[(t >> 5) + 8] = ss; }
    __syncthreads();
    float S = 0.f, SS = 0.f;
    #pragma unroll
    for (int i = 0; i < 8; i++) { S += sm[i]; SS += sm[i + 8]; }
    float mean = S * (1.f / 768.f);
    float var  = SS * (1.f / 768.f) - mean * mean;
    float inv  = rsqrtf(var + 1e-6f);
    dst[t]       = __float2bfloat16((v0 - mean) * inv * w[t]       + bb[t]);
    dst[t + 256] = __float2bfloat16((v1 - mean) * inv * w[t + 256] + bb[t + 256]);
    dst[t + 512] = __float2bfloat16((v2 - mean) * inv * w[t + 512] + bb[t + 512]);
}

// ---------------- bf16 mma.sync GEMM (M=8192, K=768, N=768 or 72) -------------
__device__ __forceinline__ void mma16816(float c[4], const uint32_t a[4], const uint32_t b[2]) {
    asm volatile(
        "mma.sync.aligned.m16n8k16.row.col.f32.bf16.bf16.f32 "
        "{%0,%1,%2,%3},{%4,%5,%6,%7},{%8,%9},{%0,%1,%2,%3};\n"
        : "+f"(c[0]), "+f"(c[1]), "+f"(c[2]), "+f"(c[3])
        : "r"(a[0]), "r"(a[1]), "r"(a[2]), "r"(a[3]), "r"(b[0]), "r"(b[1]));
}

// sel: 0 = f @ w_value -> g_value (bf16)
//      1 = q @ w_oa    -> g_raw   (fp32)
//      2 = sampled @ w_out, epilogue out = x + gamma*(acc+bias)  (fp32)
__global__ __launch_bounds__(256) void gemm_kernel(
    int sel, int N,
    const float* __restrict__ bias_in,
    const float* __restrict__ xres, const float* __restrict__ gamma,
    float* __restrict__ outF)
{
    const __nv_bfloat16* A  = (sel == 0) ? g_f  : (sel == 1) ? g_q   : g_sampled;
    const __nv_bfloat16* Bw = (sel == 0) ? g_wv : (sel == 1) ? g_woa : g_wo;
    const float* bias = (sel == 1) ? g_boa : bias_in;

    __shared__ __align__(16) __nv_bfloat16 As[2][128 * 40];
    __shared__ __align__(16) __nv_bfloat16 Bs[2][128 * 40];

    const int tid = threadIdx.x;
    const int warp = tid >> 5, lane = tid & 31;
    const int wr = warp >> 2, wc = warp & 3;      // 2x4 warp grid
    const int g  = lane >> 2, tg = lane & 3;
    const int mWarp = wr * 64, nWarp = wc * 32;
    const long rowBlock = (long)blockIdx.x * 128;
    const int  colBlock = blockIdx.y * 128;
    const int  K = CDIM;
    const int  nK = K / 32;                       // 24

    // global->smem tile mapping (each thread: 2x uint4 for A, 2x uint4 for B)
    const int ar0 = tid >> 2,          ac0 = (tid & 3) * 8;
    const int ar1 = (tid + 256) >> 2,  ac1 = ((tid + 256) & 3) * 8;
    const int bk0 = tid >> 4,          bn0 = (tid & 15) * 8;
    const int bk1 = (tid + 256) >> 4,  bn1 = ((tid + 256) & 15) * 8;

    float acc[4][4][4];
    #pragma unroll
    for (int i = 0; i < 4; i++)
        #pragma unroll
        for (int j = 0; j < 4; j++)
            #pragma unroll
            for (int k = 0; k < 4; k++) acc[i][j][k] = 0.f;

    uint4 pa0, pa1, pb0, pb1;
    const uint4 z4 = make_uint4(0, 0, 0, 0);

    auto fetch = [&](int kt) {
        pa0 = *(const uint4*)(A + (rowBlock + ar0) * K + kt * 32 + ac0);
        pa1 = *(const uint4*)(A + (rowBlock + ar1) * K + kt * 32 + ac1);
        pb0 = (colBlock + bn0 < N) ? *(const uint4*)(Bw + (long)(kt * 32 + bk0) * N + colBlock + bn0) : z4;
        pb1 = (colBlock + bn1 < N) ? *(const uint4*)(Bw + (long)(kt * 32 + bk1) * N + colBlock + bn1) : z4;
    };
    auto store_smem = [&](int buf) {
        *(uint4*)&As[buf][ar0 * 40 + ac0] = pa0;
        *(uint4*)&As[buf][ar1 * 40 + ac1] = pa1;
        __nv_bfloat16 t[8];
        *(uint4*)t = pb0;
        #pragma unroll
        for (int j = 0; j < 8; j++) Bs[buf][(bn0 + j) * 40 + bk0] = t[j];
        *(uint4*)t = pb1;
        #pragma unroll
        for (int j = 0; j < 8; j++) Bs[buf][(bn1 + j) * 40 + bk1] = t[j];
    };
    auto compute = [&](int buf) {
        #pragma unroll
        for (int ki = 0; ki < 2; ki++) {
            uint32_t af[4][4], bf_[4][2];
            const int c = ki * 16 + 2 * tg;
            #pragma unroll
            for (int mi = 0; mi < 4; mi++) {
                int r = mWarp + mi * 16 + g;
                af[mi][0] = *(const uint32_t*)&As[buf][ r      * 40 + c];
                af[mi][1] = *(const uint32_t*)&As[buf][(r + 8) * 40 + c];
                af[mi][2] = *(const uint32_t*)&As[buf][ r      * 40 + c + 8];
                af[mi][3] = *(const uint32_t*)&As[buf][(r + 8) * 40 + c + 8];
            }
            #pragma unroll
            for (int ni = 0; ni < 4; ni++) {
                int n = nWarp + ni * 8 + g;
                bf_[ni][0] = *(const uint32_t*)&Bs[buf][n * 40 + c];
                bf_[ni][1] = *(const uint32_t*)&Bs[buf][n * 40 + c + 8];
            }
            #pragma unroll
            for (int mi = 0; mi < 4; mi++)
                #pragma unroll
                for (int ni = 0; ni < 4; ni++)
                    mma16816(acc[mi][ni], af[mi], bf_[ni]);
        }
    };

    fetch(0);
    store_smem(0);
    __syncthreads();
    for (int kt = 0; kt < nK; kt++) {
        int buf = kt & 1;
        if (kt + 1 < nK) fetch(kt + 1);
        compute(buf);
        if (kt + 1 < nK) store_smem(buf ^ 1);
        __syncthreads();
    }

    // epilogue
    auto emit = [&](int r, int c, float v) {
        if (c >= N) return;
        float bv = bias[c];
        if (sel == 0) {
            g_value[(long)r * N + c] = __float2bfloat16(v + bv);
        } else if (sel == 1) {
            g_raw[(long)r * NOA + c] = v + bv;
        } else {
            long idx = (long)r * CDIM + c;
            outF[idx] = xres[idx] + gamma[c] * (v + bv);
        }
    };
    #pragma unroll
    for (int mi = 0; mi < 4; mi++)
        #pragma unroll
        for (int ni = 0; ni < 4; ni++) {
            int rBase = (int)rowBlock + mWarp + mi * 16 + g;
            int cBase = colBlock + nWarp + ni * 8 + 2 * tg;
            emit(rBase,     cBase,     acc[mi][ni][0]);
            emit(rBase,     cBase + 1, acc[mi][ni][1]);
            emit(rBase + 8, cBase,     acc[mi][ni][2]);
            emit(rBase + 8, cBase + 1, acc[mi][ni][3]);
        }
}

// ---------------- softmax(4) + bilinear sampling ------------------------------
__global__ void sample_kernel(const float* __restrict__ refp) {
    int row = blockIdx.x;          // b*4096 + q
    int h   = blockIdx.y;          // head
    int d   = threadIdx.x;         // 0..127
    int b   = row >> 12;
    const float* raw = g_raw + (long)row * NOA;
    float rx = refp[row * 2]     * 64.f - 0.5f;
    float ry = refp[row * 2 + 1] * 64.f - 0.5f;

    float lg0 = raw[48 + h * 4 + 0];
    float lg1 = raw[48 + h * 4 + 1];
    float lg2 = raw[48 + h * 4 + 2];
    float lg3 = raw[48 + h * 4 + 3];
    float mx = fmaxf(fmaxf(lg0, lg1), fmaxf(lg2, lg3));
    float e0 = __expf(lg0 - mx), e1 = __expf(lg1 - mx);
    float e2 = __expf(lg2 - mx), e3 = __expf(lg3 - mx);
    float inv = 1.f / (e0 + e1 + e2 + e3);
    float aw[4] = {e0 * inv, e1 * inv, e2 * inv, e3 * inv};

    const __nv_bfloat16* vb = g_value + (long)b * 4096 * CDIM + h * HD + d;
    float acc = 0.f;
    #pragma unroll
    for (int p = 0; p < 4; p++) {
        float px = rx + raw[h * 8 + p * 2];
        float py = ry + raw[h * 8 + p * 2 + 1];
        float x0f = floorf(px), y0f = floorf(py);
        float fx = px - x0f, fy = py - y0f;
        int x0 = (int)x0f, y0 = (int)y0f;
        float wts[4] = {(1.f - fy) * (1.f - fx), (1.f - fy) * fx,
                        fy * (1.f - fx),          fy * fx};
        #pragma unroll
        for (int c = 0; c < 4; c++) {
            int yy = y0 + (c >> 1), xx = x0 + (c & 1);
            if (yy >= 0 && yy < GH && xx >= 0 && xx < GW) {
                acc += aw[p] * wts[c] *
                       __bfloat162float(vb[(long)(yy * GW + xx) * CDIM]);
            }
        }
    }
    g_sampled[(long)row * CDIM + h * HD + d] = __float2bfloat16(acc);
}

// ---------------- launch ------------------------------------------------------
extern "C" void kernel_launch(void* const* d_in, const int* in_sizes, int n_in,
                              void* d_out, int out_size) {
    const float* x       = (const float*)d_in[0];
    const float* refp    = (const float*)d_in[1];
    const float* feat    = (const float*)d_in[2];
    // d_in[3] spatial_shapes, d_in[4] level_start_index: compile-time constants here
    const float* qn_w    = (const float*)d_in[5];
    const float* qn_b    = (const float*)d_in[6];
    const float* fn_w    = (const float*)d_in[7];
    const float* fn_b    = (const float*)d_in[8];
    const float* gamma   = (const float*)d_in[9];
    const float* w_value = (const float*)d_in[10];
    const float* b_value = (const float*)d_in[11];
    const float* w_off   = (const float*)d_in[12];
    const float* b_off   = (const float*)d_in[13];
    const float* w_attn  = (const float*)d_in[14];
    const float* b_attn  = (const float*)d_in[15];
    const float* w_out   = (const float*)d_in[16];
    const float* b_out   = (const float*)d_in[17];
    float* out = (float*)d_out;

    prep_kernel<<<(CDIM * CDIM + 255) / 256, 256>>>(w_value, w_out, w_off, w_attn, b_off, b_attn);
    ln_kernel<<<2 * MROWS, 256>>>(x, feat, qn_w, qn_b, fn_w, fn_b);
    gemm_kernel<<<dim3(MROWS / 128, 6), 256>>>(0, 768, b_value, nullptr, nullptr, nullptr);
    gemm_kernel<<<dim3(MROWS / 128, 1), 256>>>(1, 72, nullptr, nullptr, nullptr, nullptr);
    sample_kernel<<<dim3(MROWS, NHEAD), HD>>>(refp);
    gemm_kernel<<<dim3(MROWS / 128, 6), 256>>>(2, 768, b_out, x, gamma, out);
}

// round 4
// speedup vs baseline: 2.2882x; 2.2882x over previous
#include <cuda_runtime.h>
#include <cuda_bf16.h>
#include <cstdint>

#define BB    2
#define LQ    4096
#define CDIM  768
#define GH    64
#define GW    64
#define NHEAD 6
#define NPNT  4
#define HD    128
#define MROWS 8192      // B*Lq == B*H*W
#define NOA   72        // off(48) + attn(24) columns
#define NPAD  96        // padded N rows for small GEMM weights
#define KITERS 24       // 768 / 32
#define STAGES 4
#define STAGE_BYTES 20480   // A 128x40x2 + B 128x40x2
#define SMEM_DYN (STAGES * STAGE_BYTES)

// ---------------- scratch (device globals; no allocation allowed) -------------
__device__ __align__(16) __nv_bfloat16 g_q[MROWS * CDIM];
__device__ __align__(16) __nv_bfloat16 g_f[MROWS * CDIM];
__device__ __align__(16) __nv_bfloat16 g_value[MROWS * CDIM];
__device__ __align__(16) __nv_bfloat16 g_sampled[MROWS * CDIM];
__device__ __align__(16) float         g_raw[MROWS * NOA];
__device__ __align__(16) __nv_bfloat16 g_wvT[CDIM * CDIM];   // [N][K]
__device__ __align__(16) __nv_bfloat16 g_woT[CDIM * CDIM];   // [N][K]
__device__ __align__(16) __nv_bfloat16 g_woaT[NPAD * CDIM];  // [N=96][K]
__device__ __align__(16) float         g_boa[NPAD];

// ---------------- PTX helpers -------------------------------------------------
__device__ __forceinline__ uint32_t smem_u32(const void* p) {
    uint32_t a;
    asm("{ .reg .u64 t; cvta.to.shared.u64 t, %1; cvt.u32.u64 %0, t; }" : "=r"(a) : "l"(p));
    return a;
}
__device__ __forceinline__ void cpasync16(uint32_t s, const void* g) {
    asm volatile("cp.async.cg.shared.global [%0], [%1], 16;" :: "r"(s), "l"(g));
}
__device__ __forceinline__ void cpasync16z(uint32_t s, const void* g, int srcsz) {
    asm volatile("cp.async.cg.shared.global [%0], [%1], 16, %2;" :: "r"(s), "l"(g), "r"(srcsz));
}
#define CP_COMMIT() asm volatile("cp.async.commit_group;" ::: "memory")
#define CP_WAIT(n)  asm volatile("cp.async.wait_group %0;" :: "n"(n) : "memory")

__device__ __forceinline__ void ldsm4(uint32_t r[4], uint32_t addr) {
    asm volatile("ldmatrix.sync.aligned.m8n8.x4.shared.b16 {%0,%1,%2,%3}, [%4];"
                 : "=r"(r[0]), "=r"(r[1]), "=r"(r[2]), "=r"(r[3]) : "r"(addr));
}
__device__ __forceinline__ void mma16816(float c[4], const uint32_t a[4], uint32_t b0, uint32_t b1) {
    asm volatile(
        "mma.sync.aligned.m16n8k16.row.col.f32.bf16.bf16.f32 "
        "{%0,%1,%2,%3},{%4,%5,%6,%7},{%8,%9},{%0,%1,%2,%3};\n"
        : "+f"(c[0]), "+f"(c[1]), "+f"(c[2]), "+f"(c[3])
        : "r"(a[0]), "r"(a[1]), "r"(a[2]), "r"(a[3]), "r"(b0), "r"(b1));
}

// ---------------- prep: weight transpose + pack -------------------------------
__global__ void transpose_w(const float* __restrict__ wv, const float* __restrict__ wo) {
    __shared__ float t[32][33];
    const float* src = blockIdx.z ? wo : wv;
    __nv_bfloat16* dst = blockIdx.z ? g_woT : g_wvT;
    int bx = blockIdx.x * 32, by = blockIdx.y * 32;
    int tx = threadIdx.x, ty = threadIdx.y;                 // 32 x 8
    #pragma unroll
    for (int i = 0; i < 32; i += 8)
        t[ty + i][tx] = src[(long)(by + ty + i) * CDIM + bx + tx];
    __syncthreads();
    #pragma unroll
    for (int i = 0; i < 32; i += 8)
        dst[(long)(bx + ty + i) * CDIM + by + tx] = __float2bfloat16(t[tx][ty + i]);
}
__global__ void pack_woa(const float* __restrict__ woff, const float* __restrict__ watt,
                         const float* __restrict__ boff, const float* __restrict__ batt) {
    int i = blockIdx.x * 256 + threadIdx.x;
    if (i < NPAD * CDIM) {
        int n = i / CDIM, k = i % CDIM;
        float v = (n < 48) ? woff[k * 48 + n] : (n < NOA) ? watt[k * 24 + (n - 48)] : 0.f;
        g_woaT[i] = __float2bfloat16(v);
    }
    if (i < NPAD) g_boa[i] = (i < 48) ? boff[i] : (i < NOA) ? batt[i - 48] : 0.f;
}

// ---------------- fused dual LayerNorm ----------------------------------------
__global__ void ln_kernel(const float* __restrict__ x, const float* __restrict__ feat,
                          const float* __restrict__ qw, const float* __restrict__ qb,
                          const float* __restrict__ fw, const float* __restrict__ fb) {
    int row = blockIdx.x;
    int t = threadIdx.x;
    const float *src, *w, *bb;
    __nv_bfloat16* dst;
    if (row < MROWS) {
        src = x + (long)row * CDIM; w = qw; bb = qb; dst = g_q + (long)row * CDIM;
    } else {
        int r = row - MROWS;
        src = feat + (long)r * CDIM; w = fw; bb = fb; dst = g_f + (long)r * CDIM;
    }
    float v0 = src[t], v1 = src[t + 256], v2 = src[t + 512];
    float s  = v0 + v1 + v2;
    float ss = v0 * v0 + v1 * v1 + v2 * v2;
    #pragma unroll
    for (int o = 16; o > 0; o >>= 1) {
        s  += __shfl_xor_sync(0xffffffffu, s,  o);
        ss += __shfl_xor_sync(0xffffffffu, ss, o);
    }
    __shared__ float sm[16];
    if ((t & 31) == 0) { sm[t >> 5] = s; sm[(t >> 5) + 8] = ss; }
    __syncthreads();
    float S = 0.f, SS = 0.f;
    #pragma unroll
    for (int i = 0; i < 8; i++) { S += sm[i]; SS += sm[i + 8]; }
    float mean = S * (1.f / 768.f);
    float var  = SS * (1.f / 768.f) - mean * mean;
    float inv  = rsqrtf(var + 1e-6f);
    dst[t]       = __float2bfloat16((v0 - mean) * inv * w[t]       + bb[t]);
    dst[t + 256] = __float2bfloat16((v1 - mean) * inv * w[t + 256] + bb[t + 256]);
    dst[t + 512] = __float2bfloat16((v2 - mean) * inv * w[t + 512] + bb[t + 512]);
}

// ---------------- mma.sync GEMM, 4-stage cp.async, ldmatrix -------------------
// Tile 128Mx128N, k-chunk 32, 8 warps (2M x 4N), warp tile 64x32.
// sel 0: g_f @ wvT      -> g_value (bf16, +bias)
// sel 1: g_q @ woaT     -> g_raw   (fp32, +bias, 72 cols)
// sel 2: g_sampled @ woT, out = x + gamma*(acc+bias)
__global__ __launch_bounds__(256, 2) void gemm_tc(
    int sel,
    const float* __restrict__ bias_in,
    const float* __restrict__ xres, const float* __restrict__ gamma,
    float* __restrict__ outF)
{
    extern __shared__ __align__(16) char smem[];
    const uint32_t sa = smem_u32(smem);

    const int tid = threadIdx.x;
    const int warp = tid >> 5, lane = tid & 31;
    const int wm = warp >> 2, wn = warp & 3;       // 2 x 4 warp grid
    const int g  = lane >> 2, tg = lane & 3;
    const __nv_bfloat16* A  = (sel == 0) ? g_f   : (sel == 1) ? g_q    : g_sampled;
    const __nv_bfloat16* Bw = (sel == 0) ? g_wvT : (sel == 1) ? g_woaT : g_woT;
    const float* bias = (sel == 1) ? g_boa : bias_in;
    const int nRows = (sel == 1) ? NPAD : 128;     // valid B tile rows
    const long rowBlock = (long)blockIdx.x * 128;
    const int  colBlock = blockIdx.y * 128;

    // per-thread load coords (2 x 16B for A, 2 x 16B for B per stage)
    const int lr0 = tid >> 2,          lc0 = (tid & 3) * 8;
    const int lr1 = (tid + 256) >> 2,  lc1 = ((tid + 256) & 3) * 8;

    auto load_stage = [&](int kt, int st) {
        uint32_t abase = sa + st * STAGE_BYTES;
        uint32_t bbase = abase + 10240;
        const __nv_bfloat16* Ag = A + rowBlock * CDIM + kt * 32;
        const __nv_bfloat16* Bg = Bw + (long)colBlock * CDIM + kt * 32;
        cpasync16(abase + (lr0 * 40 + lc0) * 2, Ag + (long)lr0 * CDIM + lc0);
        cpasync16(abase + (lr1 * 40 + lc1) * 2, Ag + (long)lr1 * CDIM + lc1);
        {
            int rr = lr0 < nRows ? lr0 : 0, sz = lr0 < nRows ? 16 : 0;
            cpasync16z(bbase + (lr0 * 40 + lc0) * 2, Bg + (long)rr * CDIM + lc0, sz);
        }
        {
            int rr = lr1 < nRows ? lr1 : 0, sz = lr1 < nRows ? 16 : 0;
            cpasync16z(bbase + (lr1 * 40 + lc1) * 2, Bg + (long)rr * CDIM + lc1, sz);
        }
        CP_COMMIT();
    };

    float acc[4][4][4];
    #pragma unroll
    for (int i = 0; i < 4; i++)
        #pragma unroll
        for (int j = 0; j < 4; j++)
            #pragma unroll
            for (int k = 0; k < 4; k++) acc[i][j][k] = 0.f;

    // ldmatrix per-lane base addresses (row component)
    const uint32_t aRowOff = (uint32_t)((wm * 64 + (lane & 15)) * 40) * 2;
    const uint32_t bRowOff = (uint32_t)((wn * 32 + (lane & 15)) * 40) * 2 + 10240;
    const uint32_t kLane   = (uint32_t)((lane >> 4) * 8) * 2;

    auto compute = [&](int st) {
        uint32_t base = sa + st * STAGE_BYTES;
        #pragma unroll
        for (int kk = 0; kk < 2; kk++) {
            uint32_t kb = (uint32_t)(kk * 32) + kLane;   // bytes: kk*16 elems
            uint32_t af[4][4], bf[2][4];
            #pragma unroll
            for (int mi = 0; mi < 4; mi++)
                ldsm4(af[mi], base + aRowOff + (uint32_t)(mi * 16 * 80) + kb);
            #pragma unroll
            for (int p = 0; p < 2; p++)
                ldsm4(bf[p], base + bRowOff + (uint32_t)(p * 16 * 80) + kb);
            #pragma unroll
            for (int mi = 0; mi < 4; mi++)
                #pragma unroll
                for (int ni = 0; ni < 4; ni++)
                    mma16816(acc[mi][ni], af[mi], bf[ni >> 1][ni & 1], bf[ni >> 1][(ni & 1) + 2]);
        }
    };

    load_stage(0, 0);
    load_stage(1, 1);
    load_stage(2, 2);
    #pragma unroll 1
    for (int kt = 0; kt < KITERS; kt++) {
        CP_WAIT(2);
        __syncthreads();
        compute(kt & 3);
        if (kt + 3 < KITERS) load_stage(kt + 3, (kt + 3) & 3);
        else CP_COMMIT();     // keep group counting consistent
    }

    // ---------------- epilogue (registers -> gmem) ----------------
    #pragma unroll
    for (int mi = 0; mi < 4; mi++) {
        #pragma unroll
        for (int ni = 0; ni < 4; ni++) {
            int r0 = (int)rowBlock + wm * 64 + mi * 16 + g;
            int c0 = colBlock + wn * 32 + ni * 8 + tg * 2;
            #pragma unroll
            for (int h = 0; h < 2; h++) {       // h=0: row r0, h=1: row r0+8
                int r = r0 + h * 8;
                float v0 = acc[mi][ni][h * 2], v1 = acc[mi][ni][h * 2 + 1];
                if (sel == 0) {
                    float b0 = bias[c0], b1 = bias[c0 + 1];
                    __nv_bfloat162 t2 = __floats2bfloat162_rn(v0 + b0, v1 + b1);
                    *(__nv_bfloat162*)(g_value + (long)r * CDIM + c0) = t2;
                } else if (sel == 1) {
                    if (c0 < NOA)     g_raw[(long)r * NOA + c0]     = v0 + bias[c0];
                    if (c0 + 1 < NOA) g_raw[(long)r * NOA + c0 + 1] = v1 + bias[c0 + 1];
                } else {
                    long idx = (long)r * CDIM + c0;
                    float2 xr = *(const float2*)(xres + idx);
                    float2 o;
                    o.x = xr.x + gamma[c0]     * (v0 + bias[c0]);
                    o.y = xr.y + gamma[c0 + 1] * (v1 + bias[c0 + 1]);
                    *(float2*)(outF + idx) = o;
                }
            }
        }
    }
}

// ---------------- softmax(4) + bilinear sampling ------------------------------
// one block per row, 384 threads = 6 heads x 64 lanes, 2 d per lane
__global__ void sample_kernel(const float* __restrict__ refp) {
    int row = blockIdx.x;
    int t = threadIdx.x;
    int h = t >> 6, d2 = (t & 63) * 2;
    int b = row >> 12;
    const float* raw = g_raw + (long)row * NOA;
    float rx = refp[row * 2]     * 64.f - 0.5f;
    float ry = refp[row * 2 + 1] * 64.f - 0.5f;

    float lg0 = raw[48 + h * 4 + 0];
    float lg1 = raw[48 + h * 4 + 1];
    float lg2 = raw[48 + h * 4 + 2];
    float lg3 = raw[48 + h * 4 + 3];
    float mx = fmaxf(fmaxf(lg0, lg1), fmaxf(lg2, lg3));
    float e0 = __expf(lg0 - mx), e1 = __expf(lg1 - mx);
    float e2 = __expf(lg2 - mx), e3 = __expf(lg3 - mx);
    float inv = 1.f / (e0 + e1 + e2 + e3);
    float aw[4] = {e0 * inv, e1 * inv, e2 * inv, e3 * inv};

    const __nv_bfloat16* vb = g_value + (long)b * 4096 * CDIM + h * HD + d2;
    float ax = 0.f, ay = 0.f;
    #pragma unroll
    for (int p = 0; p < 4; p++) {
        float px = rx + raw[h * 8 + p * 2];
        float py = ry + raw[h * 8 + p * 2 + 1];
        float x0f = floorf(px), y0f = floorf(py);
        float fx = px - x0f, fy = py - y0f;
        int x0 = (int)x0f, y0 = (int)y0f;
        float wts[4] = {(1.f - fy) * (1.f - fx), (1.f - fy) * fx,
                        fy * (1.f - fx),          fy * fx};
        #pragma unroll
        for (int c = 0; c < 4; c++) {
            int yy = y0 + (c >> 1), xx = x0 + (c & 1);
            if (yy >= 0 && yy < GH && xx >= 0 && xx < GW) {
                float w = aw[p] * wts[c];
                __nv_bfloat162 v2 = *(const __nv_bfloat162*)(vb + (long)(yy * GW + xx) * CDIM);
                ax += w * __bfloat162float(v2.x);
                ay += w * __bfloat162float(v2.y);
            }
        }
    }
    *(__nv_bfloat162*)(g_sampled + (long)row * CDIM + h * HD + d2) = __floats2bfloat162_rn(ax, ay);
}

// ---------------- launch ------------------------------------------------------
extern "C" void kernel_launch(void* const* d_in, const int* in_sizes, int n_in,
                              void* d_out, int out_size) {
    const float* x       = (const float*)d_in[0];
    const float* refp    = (const float*)d_in[1];
    const float* feat    = (const float*)d_in[2];
    const float* qn_w    = (const float*)d_in[5];
    const float* qn_b    = (const float*)d_in[6];
    const float* fn_w    = (const float*)d_in[7];
    const float* fn_b    = (const float*)d_in[8];
    const float* gamma   = (const float*)d_in[9];
    const float* w_value = (const float*)d_in[10];
    const float* b_value = (const float*)d_in[11];
    const float* w_off   = (const float*)d_in[12];
    const float* b_off   = (const float*)d_in[13];
    const float* w_attn  = (const float*)d_in[14];
    const float* b_attn  = (const float*)d_in[15];
    const float* w_out   = (const float*)d_in[16];
    const float* b_out   = (const float*)d_in[17];
    float* out = (float*)d_out;

    cudaFuncSetAttribute(gemm_tc, cudaFuncAttributeMaxDynamicSharedMemorySize, SMEM_DYN);

    transpose_w<<<dim3(24, 24, 2), dim3(32, 8)>>>(w_value, w_out);
    pack_woa<<<(NPAD * CDIM + 255) / 256, 256>>>(w_off, w_attn, b_off, b_attn);
    ln_kernel<<<2 * MROWS, 256>>>(x, feat, qn_w, qn_b, fn_w, fn_b);
    gemm_tc<<<dim3(64, 6), 256, SMEM_DYN>>>(0, b_value, nullptr, nullptr, nullptr);
    gemm_tc<<<dim3(64, 1), 256, SMEM_DYN>>>(1, nullptr, nullptr, nullptr, nullptr);
    sample_kernel<<<MROWS, 384>>>(refp);
    gemm_tc<<<dim3(64, 6), 256, SMEM_DYN>>>(2, b_out, x, gamma, out);
}

// round 5
// speedup vs baseline: 2.8930x; 1.2643x over previous
#include <cuda_runtime.h>
#include <cuda_bf16.h>
#include <cstdint>

#define BB    2
#define LQ    4096
#define CDIM  768
#define GH    64
#define GW    64
#define NHEAD 6
#define NPNT  4
#define HD    128
#define MROWS 8192      // B*Lq == B*H*W
#define NOA   72        // off(48) + attn(24) columns
#define NPAD  96        // padded N rows for small GEMM weights
#define KITERS 12       // 768 / 64
#define STAGES 3
#define STAGE_BYTES 32768   // A 128x128B + B 128x128B (swizzled, no pad)
#define SMEM_DYN (STAGES * STAGE_BYTES)

// ---------------- scratch (device globals; no allocation allowed) -------------
__device__ __align__(16) __nv_bfloat16 g_q[MROWS * CDIM];
__device__ __align__(16) __nv_bfloat16 g_f[MROWS * CDIM];
__device__ __align__(16) __nv_bfloat16 g_value[MROWS * CDIM];
__device__ __align__(16) __nv_bfloat16 g_sampled[MROWS * CDIM];
__device__ __align__(16) float         g_raw[MROWS * NOA];
__device__ __align__(16) __nv_bfloat16 g_wvT[CDIM * CDIM];   // [N][K]
__device__ __align__(16) __nv_bfloat16 g_woT[CDIM * CDIM];   // [N][K]
__device__ __align__(16) __nv_bfloat16 g_woaT[NPAD * CDIM];  // [N=96][K]
__device__ __align__(16) float         g_boa[NPAD];

// ---------------- PTX helpers -------------------------------------------------
__device__ __forceinline__ uint32_t smem_u32(const void* p) {
    uint32_t a;
    asm("{ .reg .u64 t; cvta.to.shared.u64 t, %1; cvt.u32.u64 %0, t; }" : "=r"(a) : "l"(p));
    return a;
}
__device__ __forceinline__ void cpasync16(uint32_t s, const void* g) {
    asm volatile("cp.async.cg.shared.global [%0], [%1], 16;" :: "r"(s), "l"(g));
}
__device__ __forceinline__ void cpasync16z(uint32_t s, const void* g, int srcsz) {
    asm volatile("cp.async.cg.shared.global [%0], [%1], 16, %2;" :: "r"(s), "l"(g), "r"(srcsz));
}
#define CP_COMMIT() asm volatile("cp.async.commit_group;" ::: "memory")
#define CP_WAIT(n)  asm volatile("cp.async.wait_group %0;" :: "n"(n) : "memory")

__device__ __forceinline__ void ldsm4(uint32_t r[4], uint32_t addr) {
    asm volatile("ldmatrix.sync.aligned.m8n8.x4.shared.b16 {%0,%1,%2,%3}, [%4];"
                 : "=r"(r[0]), "=r"(r[1]), "=r"(r[2]), "=r"(r[3]) : "r"(addr));
}
__device__ __forceinline__ void mma16816(float c[4], const uint32_t a[4], uint32_t b0, uint32_t b1) {
    asm volatile(
        "mma.sync.aligned.m16n8k16.row.col.f32.bf16.bf16.f32 "
        "{%0,%1,%2,%3},{%4,%5,%6,%7},{%8,%9},{%0,%1,%2,%3};\n"
        : "+f"(c[0]), "+f"(c[1]), "+f"(c[2]), "+f"(c[3])
        : "r"(a[0]), "r"(a[1]), "r"(a[2]), "r"(a[3]), "r"(b0), "r"(b1));
}

// ---------------- prep: weight transpose + pack -------------------------------
__global__ void transpose_w(const float* __restrict__ wv, const float* __restrict__ wo) {
    __shared__ float t[32][33];
    const float* src = blockIdx.z ? wo : wv;
    __nv_bfloat16* dst = blockIdx.z ? g_woT : g_wvT;
    int bx = blockIdx.x * 32, by = blockIdx.y * 32;
    int tx = threadIdx.x, ty = threadIdx.y;                 // 32 x 8
    #pragma unroll
    for (int i = 0; i < 32; i += 8)
        t[ty + i][tx] = src[(long)(by + ty + i) * CDIM + bx + tx];
    __syncthreads();
    #pragma unroll
    for (int i = 0; i < 32; i += 8)
        dst[(long)(bx + ty + i) * CDIM + by + tx] = __float2bfloat16(t[tx][ty + i]);
}
__global__ void pack_woa(const float* __restrict__ woff, const float* __restrict__ watt,
                         const float* __restrict__ boff, const float* __restrict__ batt) {
    int i = blockIdx.x * 256 + threadIdx.x;
    if (i < NPAD * CDIM) {
        int n = i / CDIM, k = i % CDIM;
        float v = (n < 48) ? woff[k * 48 + n] : (n < NOA) ? watt[k * 24 + (n - 48)] : 0.f;
        g_woaT[i] = __float2bfloat16(v);
    }
    if (i < NPAD) g_boa[i] = (i < 48) ? boff[i] : (i < NOA) ? batt[i - 48] : 0.f;
}

// ---------------- fused dual LayerNorm ----------------------------------------
__global__ void ln_kernel(const float* __restrict__ x, const float* __restrict__ feat,
                          const float* __restrict__ qw, const float* __restrict__ qb,
                          const float* __restrict__ fw, const float* __restrict__ fb) {
    int row = blockIdx.x;
    int t = threadIdx.x;
    const float *src, *w, *bb;
    __nv_bfloat16* dst;
    if (row < MROWS) {
        src = x + (long)row * CDIM; w = qw; bb = qb; dst = g_q + (long)row * CDIM;
    } else {
        int r = row - MROWS;
        src = feat + (long)r * CDIM; w = fw; bb = fb; dst = g_f + (long)r * CDIM;
    }
    float v0 = src[t], v1 = src[t + 256], v2 = src[t + 512];
    float s  = v0 + v1 + v2;
    float ss = v0 * v0 + v1 * v1 + v2 * v2;
    #pragma unroll
    for (int o = 16; o > 0; o >>= 1) {
        s  += __shfl_xor_sync(0xffffffffu, s,  o);
        ss += __shfl_xor_sync(0xffffffffu, ss, o);
    }
    __shared__ float sm[16];
    if ((t & 31) == 0) { sm[t >> 5] = s; sm[(t >> 5) + 8] = ss; }
    __syncthreads();
    float S = 0.f, SS = 0.f;
    #pragma unroll
    for (int i = 0; i < 8; i++) { S += sm[i]; SS += sm[i + 8]; }
    float mean = S * (1.f / 768.f);
    float var  = SS * (1.f / 768.f) - mean * mean;
    float inv  = rsqrtf(var + 1e-6f);
    dst[t]       = __float2bfloat16((v0 - mean) * inv * w[t]       + bb[t]);
    dst[t + 256] = __float2bfloat16((v1 - mean) * inv * w[t + 256] + bb[t + 256]);
    dst[t + 512] = __float2bfloat16((v2 - mean) * inv * w[t + 512] + bb[t + 512]);
}

// ---------------- mma.sync GEMM, 3-stage cp.async, k-chunk 64, swizzled -------
// Tile 128Mx128N, 8 warps (2M x 4N), warp tile 64x32.
// sel 0: y<6: g_f @ wvT -> g_value (bf16,+bias); y==6: g_q @ woaT -> g_raw (fp32)
// sel 2: g_sampled @ woT, out = x + gamma*(acc+bias)
__global__ __launch_bounds__(256, 2) void gemm_tc(
    int sel,
    const float* __restrict__ bias_in,
    const float* __restrict__ xres, const float* __restrict__ gamma,
    float* __restrict__ outF)
{
    extern __shared__ __align__(16) char smem[];
    const uint32_t sa = smem_u32(smem);

    const int tid = threadIdx.x;
    const int warp = tid >> 5, lane = tid & 31;
    const int wm = warp >> 2, wn = warp & 3;       // 2 x 4 warp grid
    const int g  = lane >> 2, tg = lane & 3;
    const bool small = (sel == 0) && (blockIdx.y == 6);
    const __nv_bfloat16* A  = small ? g_q : (sel == 0) ? g_f : g_sampled;
    const __nv_bfloat16* Bw = small ? g_woaT : (sel == 0) ? g_wvT : g_woT;
    const float* bias = small ? g_boa : bias_in;
    const int nRows = small ? NPAD : 128;          // valid B tile rows
    const long rowBlock = (long)blockIdx.x * 128;
    const int  colBlock = small ? 0 : blockIdx.y * 128;

    // cp.async coords: 4 chunks of 16B for A, 4 for B per stage per thread
    const int cr = tid >> 3, cc = tid & 7;         // base row (stride 32), chunk col

    auto load_stage = [&](int kt, int st) {
        uint32_t abase = sa + st * STAGE_BYTES;
        uint32_t bbase = abase + 16384;
        const __nv_bfloat16* Ag = A + rowBlock * CDIM + kt * 64;
        const __nv_bfloat16* Bg = Bw + (long)colBlock * CDIM + kt * 64;
        #pragma unroll
        for (int j = 0; j < 4; j++) {
            int r = cr + j * 32;
            uint32_t dst = (uint32_t)(r * 128 + ((cc ^ (r & 7)) * 16));
            cpasync16(abase + dst, Ag + (long)r * CDIM + cc * 8);
            int sz = (r < nRows) ? 16 : 0;
            int rr = (r < nRows) ? r : 0;
            cpasync16z(bbase + dst, Bg + (long)rr * CDIM + cc * 8, sz);
        }
        CP_COMMIT();
    };

    float acc[4][4][4];
    #pragma unroll
    for (int i = 0; i < 4; i++)
        #pragma unroll
        for (int j = 0; j < 4; j++)
            #pragma unroll
            for (int k = 0; k < 4; k++) acc[i][j][k] = 0.f;

    // ldmatrix per-lane precomputed addresses
    const int l15 = lane & 15, ls = lane >> 4, l7 = lane & 7;
    const uint32_t aRowB = (uint32_t)((wm * 64 + l15) * 128);
    const uint32_t bRowB = (uint32_t)((wn * 32 + l15) * 128) + 16384;
    uint32_t colT[4];
    #pragma unroll
    for (int kk = 0; kk < 4; kk++)
        colT[kk] = (uint32_t)(((kk * 2 + ls) ^ l7) * 16);

    auto compute = [&](int st) {
        uint32_t base = sa + st * STAGE_BYTES;
        uint32_t aB = base + aRowB, bB = base + bRowB;
        #pragma unroll
        for (int kk = 0; kk < 4; kk++) {
            uint32_t ct = colT[kk];
            uint32_t af[4][4], bf[2][4];
            #pragma unroll
            for (int mi = 0; mi < 4; mi++)
                ldsm4(af[mi], aB + (uint32_t)(mi * 2048) + ct);
            #pragma unroll
            for (int p = 0; p < 2; p++)
                ldsm4(bf[p], bB + (uint32_t)(p * 2048) + ct);
            #pragma unroll
            for (int mi = 0; mi < 4; mi++)
                #pragma unroll
                for (int ni = 0; ni < 4; ni++)
                    mma16816(acc[mi][ni], af[mi], bf[ni >> 1][ni & 1], bf[ni >> 1][(ni & 1) + 2]);
        }
    };

    load_stage(0, 0);
    load_stage(1, 1);
    #pragma unroll 1
    for (int kt = 0; kt < KITERS; kt++) {
        CP_WAIT(1);
        __syncthreads();
        compute(kt % 3);
        if (kt + 2 < KITERS) load_stage(kt + 2, (kt + 2) % 3);
        else CP_COMMIT();     // keep group counting consistent
    }

    // ---------------- epilogue (registers -> gmem) ----------------
    #pragma unroll
    for (int mi = 0; mi < 4; mi++) {
        #pragma unroll
        for (int ni = 0; ni < 4; ni++) {
            int r0 = (int)rowBlock + wm * 64 + mi * 16 + g;
            int c0 = colBlock + wn * 32 + ni * 8 + tg * 2;
            #pragma unroll
            for (int h = 0; h < 2; h++) {       // h=0: row r0, h=1: row r0+8
                int r = r0 + h * 8;
                float v0 = acc[mi][ni][h * 2], v1 = acc[mi][ni][h * 2 + 1];
                if (small) {
                    if (c0 < NOA)     g_raw[(long)r * NOA + c0]     = v0 + bias[c0];
                    if (c0 + 1 < NOA) g_raw[(long)r * NOA + c0 + 1] = v1 + bias[c0 + 1];
                } else if (sel == 0) {
                    float b0 = bias[c0], b1 = bias[c0 + 1];
                    __nv_bfloat162 t2 = __floats2bfloat162_rn(v0 + b0, v1 + b1);
                    *(__nv_bfloat162*)(g_value + (long)r * CDIM + c0) = t2;
                } else {
                    long idx = (long)r * CDIM + c0;
                    float2 xr = *(const float2*)(xres + idx);
                    float2 o;
                    o.x = xr.x + gamma[c0]     * (v0 + bias[c0]);
                    o.y = xr.y + gamma[c0 + 1] * (v1 + bias[c0 + 1]);
                    *(float2*)(outF + idx) = o;
                }
            }
        }
    }
}

// ---------------- softmax(4) + bilinear sampling ------------------------------
// one block per row, 384 threads = 6 heads x 64 lanes, 2 d per lane
__global__ void sample_kernel(const float* __restrict__ refp) {
    int row = blockIdx.x;
    int t = threadIdx.x;
    int h = t >> 6, d2 = (t & 63) * 2;
    int b = row >> 12;
    const float* raw = g_raw + (long)row * NOA;
    float rx = refp[row * 2]     * 64.f - 0.5f;
    float ry = refp[row * 2 + 1] * 64.f - 0.5f;

    float lg0 = raw[48 + h * 4 + 0];
    float lg1 = raw[48 + h * 4 + 1];
    float lg2 = raw[48 + h * 4 + 2];
    float lg3 = raw[48 + h * 4 + 3];
    float mx = fmaxf(fmaxf(lg0, lg1), fmaxf(lg2, lg3));
    float e0 = __expf(lg0 - mx), e1 = __expf(lg1 - mx);
    float e2 = __expf(lg2 - mx), e3 = __expf(lg3 - mx);
    float inv = 1.f / (e0 + e1 + e2 + e3);
    float aw[4] = {e0 * inv, e1 * inv, e2 * inv, e3 * inv};

    const __nv_bfloat16* vb = g_value + (long)b * 4096 * CDIM + h * HD + d2;
    float ax = 0.f, ay = 0.f;
    #pragma unroll
    for (int p = 0; p < 4; p++) {
        float px = rx + raw[h * 8 + p * 2];
        float py = ry + raw[h * 8 + p * 2 + 1];
        float x0f = floorf(px), y0f = floorf(py);
        float fx = px - x0f, fy = py - y0f;
        int x0 = (int)x0f, y0 = (int)y0f;
        float wts[4] = {(1.f - fy) * (1.f - fx), (1.f - fy) * fx,
                        fy * (1.f - fx),          fy * fx};
        #pragma unroll
        for (int c = 0; c < 4; c++) {
            int yy = y0 + (c >> 1), xx = x0 + (c & 1);
            if (yy >= 0 && yy < GH && xx >= 0 && xx < GW) {
                float w = aw[p] * wts[c];
                __nv_bfloat162 v2 = *(const __nv_bfloat162*)(vb + (long)(yy * GW + xx) * CDIM);
                ax += w * __bfloat162float(v2.x);
                ay += w * __bfloat162float(v2.y);
            }
        }
    }
    *(__nv_bfloat162*)(g_sampled + (long)row * CDIM + h * HD + d2) = __floats2bfloat162_rn(ax, ay);
}

// ---------------- launch ------------------------------------------------------
extern "C" void kernel_launch(void* const* d_in, const int* in_sizes, int n_in,
                              void* d_out, int out_size) {
    const float* x       = (const float*)d_in[0];
    const float* refp    = (const float*)d_in[1];
    const float* feat    = (const float*)d_in[2];
    const float* qn_w    = (const float*)d_in[5];
    const float* qn_b    = (const float*)d_in[6];
    const float* fn_w    = (const float*)d_in[7];
    const float* fn_b    = (const float*)d_in[8];
    const float* gamma   = (const float*)d_in[9];
    const float* w_value = (const float*)d_in[10];
    const float* b_value = (const float*)d_in[11];
    const float* w_off   = (const float*)d_in[12];
    const float* b_off   = (const float*)d_in[13];
    const float* w_attn  = (const float*)d_in[14];
    const float* b_attn  = (const float*)d_in[15];
    const float* w_out   = (const float*)d_in[16];
    const float* b_out   = (const float*)d_in[17];
    float* out = (float*)d_out;

    cudaFuncSetAttribute(gemm_tc, cudaFuncAttributeMaxDynamicSharedMemorySize, SMEM_DYN);

    transpose_w<<<dim3(24, 24, 2), dim3(32, 8)>>>(w_value, w_out);
    pack_woa<<<(NPAD * CDIM + 255) / 256, 256>>>(w_off, w_attn, b_off, b_attn);
    ln_kernel<<<2 * MROWS, 256>>>(x, feat, qn_w, qn_b, fn_w, fn_b);
    gemm_tc<<<dim3(64, 7), 256, SMEM_DYN>>>(0, b_value, nullptr, nullptr, nullptr);
    sample_kernel<<<MROWS, 384>>>(refp);
    gemm_tc<<<dim3(64, 6), 256, SMEM_DYN>>>(2, b_out, x, gamma, out);
}